// round 10
// baseline (speedup 1.0000x reference)
#include <cuda_runtime.h>
#include <cstdint>

#define BB   32
#define CIN  256
#define HH   56
#define WWD  56
#define COUT 256
#define NK   4
#define HID  64

#define CIC   32            // ci per stage
#define NSTG  (CIN/CIC)     // 8
#define PADW  40            // padded ci-stride in sx
#define NROWS 4             // output rows per CTA
#define NTAP  72            // NSTG*9 global tap steps

// -------- scratch (device globals) --------
__device__ float g_v[BB*CIN];
__device__ float g_a[BB*NK];
// mixed weights (tf32), fragment-permuted:
// [b][tap][ct(2)][stage(8)][co_t(8)][k_t(4)][lane(32)][v(4)]
__device__ __align__(16) float g_wa[(size_t)BB*9*COUT*CIN];

// ===================== helpers =====================
__device__ __forceinline__ uint32_t smem_u32(const void* p) {
    uint32_t a;
    asm("{ .reg .u64 t; cvta.to.shared.u64 t, %1; cvt.u32.u64 %0, t; }" : "=r"(a) : "l"(p));
    return a;
}
__device__ __forceinline__ uint32_t f2tf32(float f) {
    uint32_t r;
    asm("cvt.rna.tf32.f32 %0, %1;" : "=r"(r) : "f"(f));
    return r;
}
__device__ __forceinline__ void mma_tf32(float* c, const uint32_t* a, const uint32_t* b) {
    asm volatile("mma.sync.aligned.m16n8k8.row.col.f32.tf32.tf32.f32 "
        "{%0,%1,%2,%3}, {%4,%5,%6,%7}, {%8,%9}, {%0,%1,%2,%3};"
        : "+f"(c[0]), "+f"(c[1]), "+f"(c[2]), "+f"(c[3])
        : "r"(a[0]), "r"(a[1]), "r"(a[2]), "r"(a[3]), "r"(b[0]), "r"(b[1]));
}
#define CP_ASYNC16(dst, src) \
    asm volatile("cp.async.ca.shared.global [%0], [%1], 16;" :: "r"(dst), "l"(src) : "memory")
#define CP_COMMIT() asm volatile("cp.async.commit_group;" ::: "memory")
#define CP_WAIT0()  asm volatile("cp.async.wait_group 0;" ::: "memory")

#define LDSV4(r0,r1,r2,r3,a) \
    asm volatile("ld.shared.v4.u32 {%0,%1,%2,%3}, [%4];" : "=r"(r0),"=r"(r1),"=r"(r2),"=r"(r3) : "r"(a))
#define LDSV2(r0,r1,a) \
    asm volatile("ld.shared.v2.u32 {%0,%1}, [%2];" : "=r"(r0),"=r"(r1) : "r"(a))

// ===================== 1) global average pool =====================
__global__ void gap_kernel(const float* __restrict__ x) {
    int bc = blockIdx.x;
    const float* p = x + (size_t)bc * (HH*WWD);
    float s = 0.f;
    for (int i = threadIdx.x; i < HH*WWD; i += 256) s += p[i];
    __shared__ float red[256];
    red[threadIdx.x] = s;
    __syncthreads();
    for (int off = 128; off > 0; off >>= 1) {
        if (threadIdx.x < off) red[threadIdx.x] += red[threadIdx.x + off];
        __syncthreads();
    }
    if (threadIdx.x == 0) g_v[bc] = red[0] * (1.0f / (HH*WWD));
}

// ===================== 2) router MLP + softmax =====================
__global__ void router_kernel(const float* __restrict__ fc1w, const float* __restrict__ fc1b,
                              const float* __restrict__ fc2w, const float* __restrict__ fc2b) {
    int b = blockIdx.x;
    __shared__ float sv[CIN];
    __shared__ float sh[HID];
    __shared__ float sl[NK];
    for (int i = threadIdx.x; i < CIN; i += 64) sv[i] = g_v[b*CIN + i];
    __syncthreads();
    int j = threadIdx.x;
    float acc = fc1b[j];
    for (int c = 0; c < CIN; c++) acc += sv[c] * fc1w[j*CIN + c];
    sh[j] = acc > 0.f ? acc : 0.f;
    __syncthreads();
    if (j < NK) {
        float l = fc2b[j];
        for (int t = 0; t < HID; t++) l += sh[t] * fc2w[j*HID + t];
        sl[j] = l;
    }
    __syncthreads();
    if (j == 0) {
        float m = sl[0];
        for (int k = 1; k < NK; k++) m = fmaxf(m, sl[k]);
        float e[NK], ssum = 0.f;
        for (int k = 0; k < NK; k++) { e[k] = expf(sl[k] - m); ssum += e[k]; }
        float inv = 1.0f / ssum;
        for (int k = 0; k < NK; k++) g_a[b*NK + k] = e[k] * inv;
    }
}

// ===================== 3) mix banks -> fragment-permuted g_wa (tf32) =====================
// one block per co; all 32 samples processed with banks held in smem (wb read ONCE).
__global__ void mix_kernel(const float* __restrict__ wb) {
    __shared__ float s[NK][CIN*9];
    __shared__ float sa[BB*NK];
    int co = blockIdx.x;
    for (int idx = threadIdx.x; idx < NK*CIN*9; idx += 256) {
        int k = idx / (CIN*9);
        int jj = idx - k * (CIN*9);
        s[k][jj] = wb[((size_t)k*COUT + co)*(CIN*9) + jj];
    }
    if (threadIdx.x < BB*NK) sa[threadIdx.x] = g_a[threadIdx.x];
    int ct = co >> 7, co_t = (co >> 4) & 7, r = co & 15;
    __syncthreads();
    for (int b = 0; b < BB; b++) {
        float a0 = sa[b*NK+0], a1 = sa[b*NK+1], a2 = sa[b*NK+2], a3 = sa[b*NK+3];
        for (int idx = threadIdx.x; idx < 9*CIN; idx += 256) {
            int tap = idx >> 8;
            int ci  = idx & 255;
            int src = ci*9 + tap;
            float v = a0*s[0][src] + a1*s[1][src] + a2*s[2][src] + a3*s[3][src];
            int stage = ci >> 5, k_t = (ci >> 3) & 3, cc = ci & 7;
            int lane = (r & 7)*4 + (cc & 3);
            int vv   = ((r >> 3) & 1) + 2*((cc >> 2) & 1);
            size_t dst = ((((((((size_t)b*9 + tap)*2 + ct)*8 + stage)*8 + co_t)*4 + k_t)*32 + lane)*4) + vv;
            g_wa[dst] = __uint_as_float(f2tf32(v));
        }
    }
}

// ===================== 4) conv: tf32 mma.sync implicit GEMM =====================
// grid (14 row-quads, 2 co-halves, 32 b), 256 threads (8 warps), 2 CTAs/SM (16 warps).
// Block tile: 128 co x (4 rows x 56); warps = 2 co-halves x 4 rows.
// Warp tile: 64 co x 56 px (4 m16 x 7 n8). sx shared by all 8 warps.

#define SX_FLOATS (6*58*PADW)               // 13920 (55.7KB)
#define SA_FLOATS (8*4*32*4)                // 4096 per buffer (16KB: 8 co_t)
#define SMEM_SZ   ((SX_FLOATS + 2*SA_FLOATS) * 4)   // 88448 B

__global__ void __launch_bounds__(256, 2)
conv_kernel(const float* __restrict__ x, float* __restrict__ out) {
    extern __shared__ float smem[];
    float* sx = smem;                        // [r(6)][iw(58)][ci_perm pad 40]
    float* sA = smem + SX_FLOATS;            // [2][co_t(8)][k_t(4)][lane(32)][4]
    uint32_t sxaddr = smem_u32(sx);
    uint32_t saddrA = smem_u32(sA);

    int tid = threadIdx.x, lane = tid & 31, wid = tid >> 5;
    int lane4 = lane & 3, laneq = lane >> 2;
    int nt4 = blockIdx.x, ct = blockIdx.y, b = blockIdx.z;
    int h0 = nt4 * NROWS;
    int mhalf = wid & 1;                     // co 64-half within the 128 tile
    int orow  = wid >> 1;                    // output row 0..3

    // hoisted per-thread fragment bases
    uint32_t aLane = saddrA + (uint32_t)(lane * 16) + (uint32_t)(mhalf * 4 * 4 * 32 * 16);
    uint32_t bLane = (uint32_t)((laneq * PADW + lane4 * 2) * 4);

    float c[4][7][4];
    #pragma unroll
    for (int i = 0; i < 4; i++)
        #pragma unroll
        for (int j = 0; j < 7; j++)
            #pragma unroll
            for (int q = 0; q < 4; q++) c[i][j][q] = 0.f;

    // prologue: prefetch A(g=0) into buf 0 (4096 float4 slots / 256 thr = 4 each... 1024 slots)
    {
        const float* src = g_wa + ((((size_t)b*9 + 0)*2 + ct)*8 + 0) * (size_t)SA_FLOATS;
        #pragma unroll
        for (int it = 0; it < 4; it++) {
            int u = it*256 + tid;            // 0..1023 float4 slots
            CP_ASYNC16(saddrA + (uint32_t)(u*16), src + u*4);
        }
        CP_COMMIT();
    }

    for (int s = 0; s < NSTG; s++) {
        int ci0 = s * CIC;
        // ---- stage sx: 6 rows x 58 cols x 32 ci (k-interleaved), tf32-converted
        for (int u = tid; u < 6*14*32; u += 256) {
            int r  = u / (14*32);
            int rm = u - r * (14*32);
            int q  = rm >> 5;
            int ci = rm & 31;
            int h  = h0 - 1 + r;
            float4 v = make_float4(0.f, 0.f, 0.f, 0.f);
            if (h >= 0 && h < HH)
                v = *(const float4*)(x + ((size_t)(b*CIN + ci0 + ci)*HH + h)*WWD + q*4);
            int p = (ci & 24) + (ci & 3)*2 + ((ci >> 2) & 1);
            float* d = sx + (r*58 + 1 + q*4)*PADW + p;
            d[0*PADW] = __uint_as_float(f2tf32(v.x));
            d[1*PADW] = __uint_as_float(f2tf32(v.y));
            d[2*PADW] = __uint_as_float(f2tf32(v.z));
            d[3*PADW] = __uint_as_float(f2tf32(v.w));
        }
        for (int u = tid; u < 6*2*32; u += 256) {
            int r  = u >> 6;
            int rm = u & 63;
            int e  = rm >> 5;
            int ci = rm & 31;
            sx[(r*58 + e*57)*PADW + ci] = 0.f;
        }
        CP_WAIT0();          // A(s*9) landed
        __syncthreads();     // sx + A visible to all warps

        for (int t = 0; t < 9; t++) {
            int g = s*9 + t;
            int buf = g & 1;
            // ---- issue prefetch of A(g+1) into other buffer
            if (g + 1 < NTAP) {
                int gn = g + 1;
                int sn = gn / 9, tn = gn - sn*9;
                const float* src = g_wa + ((((size_t)b*9 + tn)*2 + ct)*8 + sn) * (size_t)SA_FLOATS;
                uint32_t dstb = saddrA + (uint32_t)(((gn & 1) * SA_FLOATS) * 4);
                #pragma unroll
                for (int it = 0; it < 4; it++) {
                    int u = it*256 + tid;
                    CP_ASYNC16(dstb + (uint32_t)(u*16), src + u*4);
                }
                CP_COMMIT();
            }

            // ---- compute tap g on buf
            int dy = t / 3, dx = t - dy * 3;
            uint32_t sxw = sxaddr + (uint32_t)((((orow + dy)*58 + dx) * PADW) * 4) + bLane;
            uint32_t sAb = aLane + (uint32_t)((buf * SA_FLOATS) * 4);

            #pragma unroll
            for (int kk = 0; kk < 4; kk++) {
                uint32_t a[4][4];
                #pragma unroll
                for (int mt = 0; mt < 4; mt++)
                    LDSV4(a[mt][0], a[mt][1], a[mt][2], a[mt][3],
                          sAb + (uint32_t)((mt*4 + kk)*512));
                #pragma unroll
                for (int nt = 0; nt < 7; nt++) {
                    uint32_t bf[2];
                    LDSV2(bf[0], bf[1], sxw + (uint32_t)(nt*8*PADW*4 + kk*32));
                    mma_tf32(c[0][nt], a[0], bf);
                    mma_tf32(c[1][nt], a[1], bf);
                    mma_tf32(c[2][nt], a[2], bf);
                    mma_tf32(c[3][nt], a[3], bf);
                }
            }

            if (t < 8) {
                CP_WAIT0();     // A(g+1) landed
                __syncthreads();// release overwritten buffer
            }
        }
    }

    // ---- epilogue: float2 stores
    int h = h0 + orow;
    #pragma unroll
    for (int mt = 0; mt < 4; mt++) {
        int co_base = ct*128 + mhalf*64 + mt*16 + laneq;
        #pragma unroll
        for (int half = 0; half < 2; half++) {
            int co = co_base + half*8;
            float* plane = out + ((size_t)(b*COUT + co)*HH + h)*WWD;
            #pragma unroll
            for (int nt = 0; nt < 7; nt++) {
                int wcol = nt*8 + lane4*2;
                *(float2*)(plane + wcol) = make_float2(c[mt][nt][half*2], c[mt][nt][half*2 + 1]);
            }
        }
    }
}

// ===================== launch =====================
extern "C" void kernel_launch(void* const* d_in, const int* in_sizes, int n_in,
                              void* d_out, int out_size) {
    const float* x    = (const float*)d_in[0];
    const float* wb   = (const float*)d_in[1];
    const float* fc1w = (const float*)d_in[2];
    const float* fc1b = (const float*)d_in[3];
    const float* fc2w = (const float*)d_in[4];
    const float* fc2b = (const float*)d_in[5];
    float* out = (float*)d_out;

    cudaFuncSetAttribute(conv_kernel, cudaFuncAttributeMaxDynamicSharedMemorySize, SMEM_SZ);
    cudaFuncSetAttribute(conv_kernel, cudaFuncAttributePreferredSharedMemoryCarveout,
                         cudaSharedmemCarveoutMaxShared);

    gap_kernel<<<BB*CIN, 256>>>(x);
    router_kernel<<<BB, 64>>>(fc1w, fc1b, fc2w, fc2b);
    mix_kernel<<<COUT, 256>>>(wb);
    conv_kernel<<<dim3(HH/NROWS, 2, BB), 256, SMEM_SZ>>>(x, out);
}

// round 11
// speedup vs baseline: 1.4162x; 1.4162x over previous
#include <cuda_runtime.h>
#include <cstdint>

#define BB   32
#define CIN  256
#define HH   56
#define WWD  56
#define COUT 256
#define NK   4
#define HID  64

#define CIC   32            // ci per stage
#define NSTG  (CIN/CIC)     // 8
#define PADW  40            // padded ci-stride in sx
#define NROWS 4             // output rows per CTA

// -------- scratch (device globals) --------
__device__ float g_v[BB*CIN];
__device__ float g_a[BB*NK];
// mixed weights (tf32), fragment-permuted:
// [b][tap][ct(4)][stage(8)][co_t(4)][k_t(4)][lane(32)][v(4)]
__device__ __align__(16) float g_wa[(size_t)BB*9*COUT*CIN];

// ===================== helpers =====================
__device__ __forceinline__ uint32_t smem_u32(const void* p) {
    uint32_t a;
    asm("{ .reg .u64 t; cvta.to.shared.u64 t, %1; cvt.u32.u64 %0, t; }" : "=r"(a) : "l"(p));
    return a;
}
__device__ __forceinline__ uint32_t f2tf32(float f) {
    uint32_t r;
    asm("cvt.rna.tf32.f32 %0, %1;" : "=r"(r) : "f"(f));
    return r;
}
__device__ __forceinline__ void mma_tf32(float* c, const uint32_t* a, const uint32_t* b) {
    asm volatile("mma.sync.aligned.m16n8k8.row.col.f32.tf32.tf32.f32 "
        "{%0,%1,%2,%3}, {%4,%5,%6,%7}, {%8,%9}, {%0,%1,%2,%3};"
        : "+f"(c[0]), "+f"(c[1]), "+f"(c[2]), "+f"(c[3])
        : "r"(a[0]), "r"(a[1]), "r"(a[2]), "r"(a[3]), "r"(b[0]), "r"(b[1]));
}
#define LDSV2(r0,r1,a) \
    asm volatile("ld.shared.v2.u32 {%0,%1}, [%2];" : "=r"(r0),"=r"(r1) : "r"(a))

// ===================== 1) global average pool =====================
__global__ void gap_kernel(const float* __restrict__ x) {
    int bc = blockIdx.x;
    const float* p = x + (size_t)bc * (HH*WWD);
    float s = 0.f;
    for (int i = threadIdx.x; i < HH*WWD; i += 256) s += p[i];
    __shared__ float red[256];
    red[threadIdx.x] = s;
    __syncthreads();
    for (int off = 128; off > 0; off >>= 1) {
        if (threadIdx.x < off) red[threadIdx.x] += red[threadIdx.x + off];
        __syncthreads();
    }
    if (threadIdx.x == 0) g_v[bc] = red[0] * (1.0f / (HH*WWD));
}

// ===================== 2) router MLP + softmax =====================
__global__ void router_kernel(const float* __restrict__ fc1w, const float* __restrict__ fc1b,
                              const float* __restrict__ fc2w, const float* __restrict__ fc2b) {
    int b = blockIdx.x;
    __shared__ float sv[CIN];
    __shared__ float sh[HID];
    __shared__ float sl[NK];
    for (int i = threadIdx.x; i < CIN; i += 64) sv[i] = g_v[b*CIN + i];
    __syncthreads();
    int j = threadIdx.x;
    float acc = fc1b[j];
    for (int c = 0; c < CIN; c++) acc += sv[c] * fc1w[j*CIN + c];
    sh[j] = acc > 0.f ? acc : 0.f;
    __syncthreads();
    if (j < NK) {
        float l = fc2b[j];
        for (int t = 0; t < HID; t++) l += sh[t] * fc2w[j*HID + t];
        sl[j] = l;
    }
    __syncthreads();
    if (j == 0) {
        float m = sl[0];
        for (int k = 1; k < NK; k++) m = fmaxf(m, sl[k]);
        float e[NK], ssum = 0.f;
        for (int k = 0; k < NK; k++) { e[k] = expf(sl[k] - m); ssum += e[k]; }
        float inv = 1.0f / ssum;
        for (int k = 0; k < NK; k++) g_a[b*NK + k] = e[k] * inv;
    }
}

// ===================== 3) mix banks -> fragment-permuted g_wa (tf32) =====================
// one block per co; all 32 samples processed with banks held in smem (wb read ONCE).
__global__ void mix_kernel(const float* __restrict__ wb) {
    __shared__ float s[NK][CIN*9];
    __shared__ float sa[BB*NK];
    int co = blockIdx.x;
    for (int idx = threadIdx.x; idx < NK*CIN*9; idx += 256) {
        int k = idx / (CIN*9);
        int jj = idx - k * (CIN*9);
        s[k][jj] = wb[((size_t)k*COUT + co)*(CIN*9) + jj];
    }
    if (threadIdx.x < BB*NK) sa[threadIdx.x] = g_a[threadIdx.x];
    int ct = co >> 6, co_t = (co >> 4) & 3, r = co & 15;
    __syncthreads();
    for (int b = 0; b < BB; b++) {
        float a0 = sa[b*NK+0], a1 = sa[b*NK+1], a2 = sa[b*NK+2], a3 = sa[b*NK+3];
        for (int idx = threadIdx.x; idx < 9*CIN; idx += 256) {
            int tap = idx >> 8;
            int ci  = idx & 255;
            int src = ci*9 + tap;
            float v = a0*s[0][src] + a1*s[1][src] + a2*s[2][src] + a3*s[3][src];
            int stage = ci >> 5, k_t = (ci >> 3) & 3, cc = ci & 7;
            int lane = (r & 7)*4 + (cc & 3);
            int vv   = ((r >> 3) & 1) + 2*((cc >> 2) & 1);
            size_t dst = ((((((((size_t)b*9 + tap)*4 + ct)*8 + stage)*4 + co_t)*4 + k_t)*32 + lane)*4) + vv;
            g_wa[dst] = __uint_as_float(f2tf32(v));
        }
    }
}

// ===================== 4) conv: tf32 mma.sync implicit GEMM =====================
// grid (14 row-quads, 4 co-quarters, 32 b), 128 threads (4 warps), 3 CTAs/SM.
// Block/warp tile: 64 co x (4 rows x 56); warp = 1 output row; 4 m16 x 7 n8.
// A fragments loaded DIRECTLY from g_wa via __ldg (no smem staging, no per-tap sync).
// Only 2 __syncthreads per ci-stage (sx produce / consume).

#define SX_FLOATS (6*58*PADW)               // 13920 (55.7KB)
#define SMEM_SZ   (SX_FLOATS * 4)

__global__ void __launch_bounds__(128, 3)
conv_kernel(const float* __restrict__ x, float* __restrict__ out) {
    extern __shared__ float smem[];
    float* sx = smem;                        // [r(6)][iw(58)][ci_perm pad 40]
    uint32_t sxaddr = smem_u32(sx);

    int tid = threadIdx.x, lane = tid & 31;
    int lane4 = lane & 3, laneq = lane >> 2;
    int nt4 = blockIdx.x, ct = blockIdx.y, b = blockIdx.z;
    int h0 = nt4 * NROWS;
    int orow = tid >> 5;                     // warp = output row 0..3

    uint32_t bLane = (uint32_t)((laneq * PADW + lane4 * 2) * 4);

    float c[4][7][4];
    #pragma unroll
    for (int i = 0; i < 4; i++)
        #pragma unroll
        for (int j = 0; j < 7; j++)
            #pragma unroll
            for (int q = 0; q < 4; q++) c[i][j][q] = 0.f;

    for (int s = 0; s < NSTG; s++) {
        int ci0 = s * CIC;
        // ---- stage sx: 6 rows x 58 cols x 32 ci (k-interleaved), tf32-converted
        for (int u = tid; u < 6*14*32; u += 128) {
            int r  = u / (14*32);
            int rm = u - r * (14*32);
            int q  = rm >> 5;
            int ci = rm & 31;
            int h  = h0 - 1 + r;
            float4 v = make_float4(0.f, 0.f, 0.f, 0.f);
            if (h >= 0 && h < HH)
                v = *(const float4*)(x + ((size_t)(b*CIN + ci0 + ci)*HH + h)*WWD + q*4);
            int p = (ci & 24) + (ci & 3)*2 + ((ci >> 2) & 1);
            float* d = sx + (r*58 + 1 + q*4)*PADW + p;
            d[0*PADW] = __uint_as_float(f2tf32(v.x));
            d[1*PADW] = __uint_as_float(f2tf32(v.y));
            d[2*PADW] = __uint_as_float(f2tf32(v.z));
            d[3*PADW] = __uint_as_float(f2tf32(v.w));
        }
        for (int u = tid; u < 6*2*32; u += 128) {
            int r  = u >> 6;
            int rm = u & 63;
            int e  = rm >> 5;
            int ci = rm & 31;
            sx[(r*58 + e*57)*PADW + ci] = 0.f;
        }
        __syncthreads();     // sx visible to all warps

        for (int t = 0; t < 9; t++) {
            int dy = t / 3, dx = t - dy * 3;
            uint32_t sxw = sxaddr + (uint32_t)((((orow + dy)*58 + dx) * PADW) * 4) + bLane;
            // per-thread A fragment base for this tap (fragment-permuted gmem)
            const float4* wab = (const float4*)(g_wa
                + ((((size_t)b*9 + t)*4 + ct)*8 + s) * 2048) + lane;

            #pragma unroll
            for (int kk = 0; kk < 4; kk++) {
                uint32_t a[4][4];
                #pragma unroll
                for (int mt = 0; mt < 4; mt++) {
                    float4 v = __ldg(wab + (mt*4 + kk)*32);
                    a[mt][0] = __float_as_uint(v.x);
                    a[mt][1] = __float_as_uint(v.y);
                    a[mt][2] = __float_as_uint(v.z);
                    a[mt][3] = __float_as_uint(v.w);
                }
                #pragma unroll
                for (int nt = 0; nt < 7; nt++) {
                    uint32_t bf[2];
                    LDSV2(bf[0], bf[1], sxw + (uint32_t)(nt*8*PADW*4 + kk*32));
                    mma_tf32(c[0][nt], a[0], bf);
                    mma_tf32(c[1][nt], a[1], bf);
                    mma_tf32(c[2][nt], a[2], bf);
                    mma_tf32(c[3][nt], a[3], bf);
                }
            }
        }
        __syncthreads();     // all warps done with sx before restaging
    }

    // ---- epilogue: float2 stores
    int h = h0 + orow;
    #pragma unroll
    for (int mt = 0; mt < 4; mt++) {
        int co_base = ct*64 + mt*16 + laneq;
        #pragma unroll
        for (int half = 0; half < 2; half++) {
            int co = co_base + half*8;
            float* plane = out + ((size_t)(b*COUT + co)*HH + h)*WWD;
            #pragma unroll
            for (int nt = 0; nt < 7; nt++) {
                int wcol = nt*8 + lane4*2;
                *(float2*)(plane + wcol) = make_float2(c[mt][nt][half*2], c[mt][nt][half*2 + 1]);
            }
        }
    }
}

// ===================== launch =====================
extern "C" void kernel_launch(void* const* d_in, const int* in_sizes, int n_in,
                              void* d_out, int out_size) {
    const float* x    = (const float*)d_in[0];
    const float* wb   = (const float*)d_in[1];
    const float* fc1w = (const float*)d_in[2];
    const float* fc1b = (const float*)d_in[3];
    const float* fc2w = (const float*)d_in[4];
    const float* fc2b = (const float*)d_in[5];
    float* out = (float*)d_out;

    cudaFuncSetAttribute(conv_kernel, cudaFuncAttributeMaxDynamicSharedMemorySize, SMEM_SZ);
    cudaFuncSetAttribute(conv_kernel, cudaFuncAttributePreferredSharedMemoryCarveout,
                         cudaSharedmemCarveoutMaxShared);

    gap_kernel<<<BB*CIN, 256>>>(x);
    router_kernel<<<BB, 64>>>(fc1w, fc1b, fc2w, fc2b);
    mix_kernel<<<COUT, 256>>>(wb);
    conv_kernel<<<dim3(HH/NROWS, 4, BB), 128, SMEM_SZ>>>(x, out);
}

// round 12
// speedup vs baseline: 1.7334x; 1.2239x over previous
#include <cuda_runtime.h>
#include <cstdint>

#define BB   32
#define CIN  256
#define HH   56
#define WWD  56
#define COUT 256
#define NK   4
#define HID  64

#define CIC   16            // ci per stage
#define NSTG  (CIN/CIC)     // 16
#define PADW  24            // padded ci-stride in sx (phase-conflict-free)
#define NROWS 4             // output rows per CTA
#define NTAP  (NSTG*9)      // 144

// -------- scratch (device globals) --------
__device__ float g_v[BB*CIN];
__device__ float g_a[BB*NK];
// mixed weights (tf32), fragment-permuted:
// [b][tap][ct(4)][stage(16)][co_t(4)][kk(2)][lane(32)][v(4)]
__device__ __align__(16) float g_wa[(size_t)BB*9*COUT*CIN];
// pre-transposed x (tf32, halo-padded, ci-permuted): [b][stage][hp(58)][iw(58)][ci(16)]
__device__ __align__(16) float g_xt[(size_t)BB*NSTG*58*58*CIC];

// ===================== helpers =====================
__device__ __forceinline__ uint32_t smem_u32(const void* p) {
    uint32_t a;
    asm("{ .reg .u64 t; cvta.to.shared.u64 t, %1; cvt.u32.u64 %0, t; }" : "=r"(a) : "l"(p));
    return a;
}
__device__ __forceinline__ uint32_t f2tf32(float f) {
    uint32_t r;
    asm("cvt.rna.tf32.f32 %0, %1;" : "=r"(r) : "f"(f));
    return r;
}
__device__ __forceinline__ void mma_tf32(float* c, const uint32_t* a, const uint32_t* b) {
    asm volatile("mma.sync.aligned.m16n8k8.row.col.f32.tf32.tf32.f32 "
        "{%0,%1,%2,%3}, {%4,%5,%6,%7}, {%8,%9}, {%0,%1,%2,%3};"
        : "+f"(c[0]), "+f"(c[1]), "+f"(c[2]), "+f"(c[3])
        : "r"(a[0]), "r"(a[1]), "r"(a[2]), "r"(a[3]), "r"(b[0]), "r"(b[1]));
}
#define CP_ASYNC16(dst, src) \
    asm volatile("cp.async.ca.shared.global [%0], [%1], 16;" :: "r"(dst), "l"(src) : "memory")
#define CP_COMMIT() asm volatile("cp.async.commit_group;" ::: "memory")
#define CP_WAIT0()  asm volatile("cp.async.wait_group 0;" ::: "memory")

#define LDSV4(r0,r1,r2,r3,a) \
    asm volatile("ld.shared.v4.u32 {%0,%1,%2,%3}, [%4];" : "=r"(r0),"=r"(r1),"=r"(r2),"=r"(r3) : "r"(a))
#define LDSV2(r0,r1,a) \
    asm volatile("ld.shared.v2.u32 {%0,%1}, [%2];" : "=r"(r0),"=r"(r1) : "r"(a))

// ===================== 1) global average pool =====================
__global__ void gap_kernel(const float* __restrict__ x) {
    int bc = blockIdx.x;
    const float* p = x + (size_t)bc * (HH*WWD);
    float s = 0.f;
    for (int i = threadIdx.x; i < HH*WWD; i += 256) s += p[i];
    __shared__ float red[256];
    red[threadIdx.x] = s;
    __syncthreads();
    for (int off = 128; off > 0; off >>= 1) {
        if (threadIdx.x < off) red[threadIdx.x] += red[threadIdx.x + off];
        __syncthreads();
    }
    if (threadIdx.x == 0) g_v[bc] = red[0] * (1.0f / (HH*WWD));
}

// ===================== 2) router MLP + softmax =====================
__global__ void router_kernel(const float* __restrict__ fc1w, const float* __restrict__ fc1b,
                              const float* __restrict__ fc2w, const float* __restrict__ fc2b) {
    int b = blockIdx.x;
    __shared__ float sv[CIN];
    __shared__ float sh[HID];
    __shared__ float sl[NK];
    for (int i = threadIdx.x; i < CIN; i += 64) sv[i] = g_v[b*CIN + i];
    __syncthreads();
    int j = threadIdx.x;
    float acc = fc1b[j];
    for (int c = 0; c < CIN; c++) acc += sv[c] * fc1w[j*CIN + c];
    sh[j] = acc > 0.f ? acc : 0.f;
    __syncthreads();
    if (j < NK) {
        float l = fc2b[j];
        for (int t = 0; t < HID; t++) l += sh[t] * fc2w[j*HID + t];
        sl[j] = l;
    }
    __syncthreads();
    if (j == 0) {
        float m = sl[0];
        for (int k = 1; k < NK; k++) m = fmaxf(m, sl[k]);
        float e[NK], ssum = 0.f;
        for (int k = 0; k < NK; k++) { e[k] = expf(sl[k] - m); ssum += e[k]; }
        float inv = 1.0f / ssum;
        for (int k = 0; k < NK; k++) g_a[b*NK + k] = e[k] * inv;
    }
}

// ===================== 2b) x transpose: x -> g_xt (tf32, padded, permuted) =====================
// grid (58 hp, 16 stage, 32 b), 128 threads.
__global__ void xpose_kernel(const float* __restrict__ x) {
    int hp = blockIdx.x, sg = blockIdx.y, b = blockIdx.z;
    float* orow = g_xt + ((size_t)(b*NSTG + sg)*58 + hp) * (58*CIC);
    int tid = threadIdx.x;
    if (hp == 0 || hp == 57) {
        for (int u = tid; u < 58*CIC; u += 128) orow[u] = 0.f;
        return;
    }
    __shared__ float tile[CIC][57];
    int h = hp - 1;
    for (int u = tid; u < CIC*WWD; u += 128) {
        int ci = u / WWD, w = u - ci*WWD;
        tile[ci][w] = x[((size_t)(b*CIN + sg*CIC + ci)*HH + h)*WWD + w];
    }
    __syncthreads();
    for (int u = tid; u < 58*CIC; u += 128) {
        int iw = u >> 4, pp = u & 15;
        float v = 0.f;
        if (iw >= 1 && iw <= 56) {
            int ci = (pp & 8) | ((pp & 1) << 2) | ((pp >> 1) & 3);   // inverse perm
            v = tile[ci][iw - 1];
        }
        orow[u] = __uint_as_float(f2tf32(v));
    }
}

// ===================== 3) mix banks -> fragment-permuted g_wa (tf32) =====================
// one block per co; all 32 samples with banks held in smem (wb read ONCE).
__global__ void mix_kernel(const float* __restrict__ wb) {
    __shared__ float s[NK][CIN*9];
    __shared__ float sa[BB*NK];
    int co = blockIdx.x;
    for (int idx = threadIdx.x; idx < NK*CIN*9; idx += 256) {
        int k = idx / (CIN*9);
        int jj = idx - k * (CIN*9);
        s[k][jj] = wb[((size_t)k*COUT + co)*(CIN*9) + jj];
    }
    if (threadIdx.x < BB*NK) sa[threadIdx.x] = g_a[threadIdx.x];
    int ct = co >> 6, co_t = (co >> 4) & 3, r = co & 15;
    __syncthreads();
    for (int b = 0; b < BB; b++) {
        float a0 = sa[b*NK+0], a1 = sa[b*NK+1], a2 = sa[b*NK+2], a3 = sa[b*NK+3];
        for (int idx = threadIdx.x; idx < 9*CIN; idx += 256) {
            int tap = idx >> 8;
            int ci  = idx & 255;
            int src = ci*9 + tap;
            float v = a0*s[0][src] + a1*s[1][src] + a2*s[2][src] + a3*s[3][src];
            int stage = ci >> 4, k_t = (ci >> 3) & 1, cc = ci & 7;
            int lane = (r & 7)*4 + (cc & 3);
            int vv   = ((r >> 3) & 1) + 2*((cc >> 2) & 1);
            size_t dst = ((((((((size_t)b*9 + tap)*4 + ct)*NSTG + stage)*4 + co_t)*2 + k_t)*32 + lane)*4) + vv;
            g_wa[dst] = __uint_as_float(f2tf32(v));
        }
    }
}

// ===================== 4) conv: tf32 mma.sync, fully-async pipeline =====================
// grid (14 row-quads, 4 co-quarters, 32 b), 128 threads (4 warps), 3 CTAs/SM.
// Warp tile: 64 co x 56 px (1 output row). sx + A both cp.async double-buffered.
// Per tap: one commit group = { A(g+1), 1/8 of sx(s+1) }, wait0 + one syncthreads.

#define SXB_FLOATS (6*58*PADW)              // 8352 per buffer (33.4KB)
#define SAB_FLOATS (4*2*32*4)               // 1024 per buffer (4KB)
#define SX_SLOTS   (6*58*4)                 // 1392 float4 slots per sx buffer
#define SX_CHUNK   (SX_SLOTS/8)             // 174 slots per tap
#define SMEM_SZ    ((2*SXB_FLOATS + 2*SAB_FLOATS) * 4)   // 75008 B

__global__ void __launch_bounds__(128, 3)
conv_kernel(float* __restrict__ out) {
    extern __shared__ float smem[];
    float* sx = smem;                        // [2][r(6)][iw(58)][ci_perm pad 24]
    float* sA = smem + 2*SXB_FLOATS;         // [2][co_t(4)][kk(2)][lane(32)][4]
    uint32_t sxaddr = smem_u32(sx);
    uint32_t saddrA = smem_u32(sA);

    int tid = threadIdx.x, lane = tid & 31;
    int lane4 = lane & 3, laneq = lane >> 2;
    int nt4 = blockIdx.x, ct = blockIdx.y, b = blockIdx.z;
    int h0 = nt4 * NROWS;
    int orow = tid >> 5;                     // warp = output row 0..3

    uint32_t bLane = (uint32_t)((laneq * PADW + lane4 * 2) * 4);
    uint32_t aLane = saddrA + (uint32_t)(lane * 16);

    float c[4][7][4];
    #pragma unroll
    for (int i = 0; i < 4; i++)
        #pragma unroll
        for (int j = 0; j < 7; j++)
            #pragma unroll
            for (int q = 0; q < 4; q++) c[i][j][q] = 0.f;

    // prologue: full sx(0) + A(0), one group
    {
        const float4* xsrc = (const float4*)(g_xt + ((size_t)(b*NSTG + 0)*58 + h0) * (58*CIC));
        for (int u = tid; u < SX_SLOTS; u += 128) {
            int rw = u >> 2, q = u & 3;      // rw = r*58+iw
            CP_ASYNC16(sxaddr + (uint32_t)((rw*PADW + q*4)*4), xsrc + u);
        }
        const float* asrc = g_wa + ((((size_t)b*9 + 0)*4 + ct)*NSTG + 0) * (size_t)SAB_FLOATS;
        #pragma unroll
        for (int it = 0; it < 2; it++) {
            int u = it*128 + tid;            // 0..255 float4 slots
            CP_ASYNC16(saddrA + (uint32_t)(u*16), asrc + u*4);
        }
        CP_COMMIT();
        CP_WAIT0();
        __syncthreads();
    }

    for (int s = 0; s < NSTG; s++) {
        for (int t = 0; t < 9; t++) {
            int g = s*9 + t;
            // ---- issue this tap's async group: A(g+1) + sx chunk t of stage s+1
            if (g + 1 < NTAP) {
                int gn = g + 1;
                int sn = gn / 9, tn = gn - sn*9;
                const float* asrc = g_wa + ((((size_t)b*9 + tn)*4 + ct)*NSTG + sn) * (size_t)SAB_FLOATS;
                uint32_t adst = saddrA + (uint32_t)(((gn & 1) * SAB_FLOATS) * 4);
                #pragma unroll
                for (int it = 0; it < 2; it++) {
                    int u = it*128 + tid;
                    CP_ASYNC16(adst + (uint32_t)(u*16), asrc + u*4);
                }
                if (t < 8 && s + 1 < NSTG) {
                    const float4* xsrc = (const float4*)(g_xt + ((size_t)(b*NSTG + s+1)*58 + h0) * (58*CIC));
                    uint32_t xdst = sxaddr + (uint32_t)((((s+1) & 1) * SXB_FLOATS) * 4);
                    int u0 = t*SX_CHUNK + tid;
                    {
                        int rw = u0 >> 2, q = u0 & 3;
                        CP_ASYNC16(xdst + (uint32_t)((rw*PADW + q*4)*4), xsrc + u0);
                    }
                    int u1 = u0 + 128;
                    if (tid < SX_CHUNK - 128) {
                        int rw = u1 >> 2, q = u1 & 3;
                        CP_ASYNC16(xdst + (uint32_t)((rw*PADW + q*4)*4), xsrc + u1);
                    }
                }
                CP_COMMIT();
            }

            // ---- compute tap g
            int dy = t / 3, dx = t - dy * 3;
            uint32_t sxw = sxaddr + (uint32_t)(((s & 1) * SXB_FLOATS) * 4)
                         + (uint32_t)((((orow + dy)*58 + dx) * PADW) * 4) + bLane;
            uint32_t sAb = aLane + (uint32_t)(((g & 1) * SAB_FLOATS) * 4);

            #pragma unroll
            for (int kk = 0; kk < 2; kk++) {
                uint32_t a[4][4];
                #pragma unroll
                for (int mt = 0; mt < 4; mt++)
                    LDSV4(a[mt][0], a[mt][1], a[mt][2], a[mt][3],
                          sAb + (uint32_t)((mt*2 + kk)*512));
                #pragma unroll
                for (int nt = 0; nt < 7; nt++) {
                    uint32_t bf[2];
                    LDSV2(bf[0], bf[1], sxw + (uint32_t)(nt*8*PADW*4 + kk*32));
                    mma_tf32(c[0][nt], a[0], bf);
                    mma_tf32(c[1][nt], a[1], bf);
                    mma_tf32(c[2][nt], a[2], bf);
                    mma_tf32(c[3][nt], a[3], bf);
                }
            }

            if (g + 1 < NTAP) {
                CP_WAIT0();
                __syncthreads();
            }
        }
    }

    // ---- epilogue: float2 stores
    int h = h0 + orow;
    #pragma unroll
    for (int mt = 0; mt < 4; mt++) {
        int co_base = ct*64 + mt*16 + laneq;
        #pragma unroll
        for (int half = 0; half < 2; half++) {
            int co = co_base + half*8;
            float* plane = out + ((size_t)(b*COUT + co)*HH + h)*WWD;
            #pragma unroll
            for (int nt = 0; nt < 7; nt++) {
                int wcol = nt*8 + lane4*2;
                *(float2*)(plane + wcol) = make_float2(c[mt][nt][half*2], c[mt][nt][half*2 + 1]);
            }
        }
    }
}

// ===================== launch =====================
extern "C" void kernel_launch(void* const* d_in, const int* in_sizes, int n_in,
                              void* d_out, int out_size) {
    const float* x    = (const float*)d_in[0];
    const float* wb   = (const float*)d_in[1];
    const float* fc1w = (const float*)d_in[2];
    const float* fc1b = (const float*)d_in[3];
    const float* fc2w = (const float*)d_in[4];
    const float* fc2b = (const float*)d_in[5];
    float* out = (float*)d_out;

    cudaFuncSetAttribute(conv_kernel, cudaFuncAttributeMaxDynamicSharedMemorySize, SMEM_SZ);
    cudaFuncSetAttribute(conv_kernel, cudaFuncAttributePreferredSharedMemoryCarveout,
                         cudaSharedmemCarveoutMaxShared);

    gap_kernel<<<BB*CIN, 256>>>(x);
    router_kernel<<<BB, 64>>>(fc1w, fc1b, fc2w, fc2b);
    xpose_kernel<<<dim3(58, NSTG, BB), 128>>>(x);
    mix_kernel<<<COUT, 256>>>(wb);
    conv_kernel<<<dim3(HH/NROWS, 4, BB), 128, SMEM_SZ>>>(out);
}